// round 3
// baseline (speedup 1.0000x reference)
#include <cuda_runtime.h>

// Volume rendering (NeRF-style) on GB300 — R2 resubmit: unit-stride rgb loads.
//
// Inputs (metadata order): rgb [N,128,3] f32, density [N,128,1] f32,
//                          distances [N,128] f32. Output: [N,3] f32.
//
// One warp per ray; 4 consecutive samples per lane for dist/density.
// Weights:
//   delta_i  = t_{i+1} - t_i   (last sample: 1e10)
//   omega_i  = exp(-density_i * delta_i)      (= 1 - alpha_i)
//   T_i      = exclusive cumprod(omega)       (warp shfl scan)
//   wt_i     = (1 - omega_i) * T_i
// wt[0..127] is staged in warp-private shared memory; rgb is then read with
// perfectly unit-stride float4 loads (flat [384] floats = 96 float4 per ray,
// 3 chunks of 32 lanes). Each float f -> sample f/3, channel f%3; a float4
// spans at most 2 samples, so 2 LDS gathers + a 3-way channel rotation.

#ifndef FULL_MASK
#define FULL_MASK 0xffffffffu
#endif

static constexpr int N_SAMPLES = 128;
static constexpr float FAR_DELTA = 1e10f;
static constexpr int WARPS_PER_BLOCK = 8;

__global__ void __launch_bounds__(WARPS_PER_BLOCK * 32, 8)
volrend_kernel(const float* __restrict__ rgb,
               const float* __restrict__ density,
               const float* __restrict__ dist,
               float* __restrict__ out,
               int n_rays)
{
    __shared__ float wt_s[WARPS_PER_BLOCK][N_SAMPLES];

    const int warp_in_block = threadIdx.x >> 5;
    const int lane          = threadIdx.x & 31;
    const int warp_id       = blockIdx.x * WARPS_PER_BLOCK + warp_in_block;
    if (warp_id >= n_rays) return;

    const long base = (long)warp_id * N_SAMPLES;

    // ---- unit-stride loads ----
    const float4 d4 = reinterpret_cast<const float4*>(dist    + base)[lane];
    const float4 s4 = reinterpret_cast<const float4*>(density + base)[lane];
    const float4* rgbv = reinterpret_cast<const float4*>(rgb + base * 3);
    const float4 v0 = rgbv[lane];           // floats [  0..127] of this ray
    const float4 v1 = rgbv[32 + lane];      // floats [128..255]
    const float4 v2 = rgbv[64 + lane];      // floats [256..383]

    // ---- deltas ----
    const float d_next = __shfl_down_sync(FULL_MASK, d4.x, 1);
    const float dl0 = d4.y - d4.x;
    const float dl1 = d4.z - d4.y;
    const float dl2 = d4.w - d4.z;
    const float dl3 = (lane == 31) ? FAR_DELTA : (d_next - d4.w);

    // ---- omega = exp(-sigma * delta) ----
    const float w0 = __expf(-s4.x * dl0);
    const float w1 = __expf(-s4.y * dl1);
    const float w2 = __expf(-s4.z * dl2);
    const float w3 = __expf(-s4.w * dl3);

    // ---- exclusive cumprod across the warp ----
    const float p = w0 * w1 * w2 * w3;
    float incl = p;
    #pragma unroll
    for (int off = 1; off < 32; off <<= 1) {
        const float v = __shfl_up_sync(FULL_MASK, incl, off);
        if (lane >= off) incl *= v;
    }
    float T = __shfl_up_sync(FULL_MASK, incl, 1);
    if (lane == 0) T = 1.0f;

    // ---- per-sample weights ----
    const float t0 = T;
    const float t1 = t0 * w0;
    const float t2 = t1 * w1;
    const float t3 = t2 * w2;
    const float wt0 = t0 - t1;
    const float wt1 = t1 - t2;
    const float wt2 = t2 - t3;
    const float wt3 = t3 * (1.0f - w3);

    // stage weights in warp-private smem row (STS.128, conflict-free)
    float* wrow = wt_s[warp_in_block];
    reinterpret_cast<float4*>(wrow)[lane] = make_float4(wt0, wt1, wt2, wt3);
    __syncwarp();

    // ---- weighted accumulation over unit-stride rgb ----
    float accR = 0.0f, accG = 0.0f, accB = 0.0f;

    #pragma unroll
    for (int c = 0; c < 3; c++) {
        const float4 v  = (c == 0) ? v0 : (c == 1) ? v1 : v2;
        const int f0 = c * N_SAMPLES + lane * 4;   // flat float index of v.x
        const int s0 = f0 / 3;
        const int b  = f0 - 3 * s0;                // f0 % 3
        const float wtA = wrow[s0];
        const float wtB = wrow[s0 + 1];
        if (b == 0) {
            // channels: x->R(s0) y->G(s0) z->B(s0) w->R(s0+1)
            accR += v.x * wtA; accG += v.y * wtA; accB += v.z * wtA;
            accR += v.w * wtB;
        } else if (b == 1) {
            // x->G(s0) y->B(s0) z->R(s0+1) w->G(s0+1)
            accG += v.x * wtA; accB += v.y * wtA;
            accR += v.z * wtB; accG += v.w * wtB;
        } else {
            // x->B(s0) y->R(s0+1) z->G(s0+1) w->B(s0+1)
            accB += v.x * wtA;
            accR += v.y * wtB; accG += v.z * wtB; accB += v.w * wtB;
        }
    }

    // ---- warp reduction ----
    #pragma unroll
    for (int off = 16; off > 0; off >>= 1) {
        accR += __shfl_xor_sync(FULL_MASK, accR, off);
        accG += __shfl_xor_sync(FULL_MASK, accG, off);
        accB += __shfl_xor_sync(FULL_MASK, accB, off);
    }

    if (lane == 0) {
        float* o = out + (long)warp_id * 3;
        o[0] = accR;
        o[1] = accG;
        o[2] = accB;
    }
}

extern "C" void kernel_launch(void* const* d_in, const int* in_sizes, int n_in,
                              void* d_out, int out_size)
{
    const float* rgb     = (const float*)d_in[0];
    const float* density = (const float*)d_in[1];
    const float* dist    = (const float*)d_in[2];
    float* out = (float*)d_out;

    const int n_rays = in_sizes[2] / N_SAMPLES;

    const int threads = WARPS_PER_BLOCK * 32;
    const int blocks = (n_rays + WARPS_PER_BLOCK - 1) / WARPS_PER_BLOCK;

    volrend_kernel<<<blocks, threads>>>(rgb, density, dist, out, n_rays);
}

// round 5
// speedup vs baseline: 1.0229x; 1.0229x over previous
#include <cuda_runtime.h>

// Volume rendering (NeRF-style) on GB300 — R4 resubmit: R1 structure +
// streaming (.cs evict-first) load hints. R2 proved the rgb access pattern
// is irrelevant: DRAM sits at ~87.5% (6.94 TB/s) under both layouts — the
// path-independent chip memory ceiling. This round minimizes instruction
// count and L2 pollution on the read-once stream.
//
// Inputs (metadata order): rgb [N,128,3] f32, density [N,128,1] f32,
//                          distances [N,128] f32. Output: [N,3] f32.
//
// One warp per ray; 4 consecutive samples per lane.
//   delta_i  = t_{i+1} - t_i   (last sample: 1e10)
//   omega_i  = exp(-density_i * delta_i)      (= 1 - alpha_i)
//   T_i      = exclusive cumprod(omega)       (warp shfl scan)
//   weight_i = (1 - omega_i) * T_i
//   out      = sum_i weight_i * rgb_i

#ifndef FULL_MASK
#define FULL_MASK 0xffffffffu
#endif

static constexpr int N_SAMPLES = 128;
static constexpr float FAR_DELTA = 1e10f;

__global__ void __launch_bounds__(256, 8)
volrend_kernel(const float* __restrict__ rgb,
               const float* __restrict__ density,
               const float* __restrict__ dist,
               float* __restrict__ out,
               int n_rays)
{
    const int warp_id = (blockIdx.x * blockDim.x + threadIdx.x) >> 5;
    const int lane    = threadIdx.x & 31;
    if (warp_id >= n_rays) return;

    const long base = (long)warp_id * N_SAMPLES;

    // ---- coalesced streaming loads: 4 samples per lane ----
    const float4 d4 = __ldcs(reinterpret_cast<const float4*>(dist    + base) + lane);
    const float4 s4 = __ldcs(reinterpret_cast<const float4*>(density + base) + lane);
    const float4* rgb4 = reinterpret_cast<const float4*>(rgb + base * 3) + lane * 3;
    const float4 c0 = __ldcs(rgb4 + 0);
    const float4 c1 = __ldcs(rgb4 + 1);
    const float4 c2 = __ldcs(rgb4 + 2);

    // ---- deltas (next lane's first distance via shfl) ----
    const float d_next = __shfl_down_sync(FULL_MASK, d4.x, 1);
    const float dl0 = d4.y - d4.x;
    const float dl1 = d4.z - d4.y;
    const float dl2 = d4.w - d4.z;
    const float dl3 = (lane == 31) ? FAR_DELTA : (d_next - d4.w);

    // ---- omega = exp(-sigma * delta) = 1 - alpha ----
    const float w0 = __expf(-s4.x * dl0);
    const float w1 = __expf(-s4.y * dl1);
    const float w2 = __expf(-s4.z * dl2);
    const float w3 = __expf(-s4.w * dl3);

    // ---- exclusive cumprod across the warp ----
    const float p = w0 * w1 * w2 * w3;     // this lane's full product
    float incl = p;                        // inclusive scan of lane products
    #pragma unroll
    for (int off = 1; off < 32; off <<= 1) {
        const float v = __shfl_up_sync(FULL_MASK, incl, off);
        if (lane >= off) incl *= v;
    }
    float T = __shfl_up_sync(FULL_MASK, incl, 1);   // exclusive: prev lane's inclusive
    if (lane == 0) T = 1.0f;

    // ---- local weights: T walks through this lane's 4 samples ----
    const float t0 = T;
    const float t1 = t0 * w0;
    const float t2 = t1 * w1;
    const float t3 = t2 * w2;
    const float wt0 = t0 - t1;             // = alpha0 * T0
    const float wt1 = t1 - t2;
    const float wt2 = t2 - t3;
    const float wt3 = t3 * (1.0f - w3);

    // rgb layout per lane: s0=(c0.x,c0.y,c0.z) s1=(c0.w,c1.x,c1.y)
    //                      s2=(c1.z,c1.w,c2.x) s3=(c2.y,c2.z,c2.w)
    float accR = wt0 * c0.x + wt1 * c0.w + wt2 * c1.z + wt3 * c2.y;
    float accG = wt0 * c0.y + wt1 * c1.x + wt2 * c1.w + wt3 * c2.z;
    float accB = wt0 * c0.z + wt1 * c1.y + wt2 * c2.x + wt3 * c2.w;

    // ---- warp reduction over the 4-sample partial sums ----
    #pragma unroll
    for (int off = 16; off > 0; off >>= 1) {
        accR += __shfl_xor_sync(FULL_MASK, accR, off);
        accG += __shfl_xor_sync(FULL_MASK, accG, off);
        accB += __shfl_xor_sync(FULL_MASK, accB, off);
    }

    if (lane == 0) {
        float* o = out + (long)warp_id * 3;
        o[0] = accR;
        o[1] = accG;
        o[2] = accB;
    }
}

extern "C" void kernel_launch(void* const* d_in, const int* in_sizes, int n_in,
                              void* d_out, int out_size)
{
    const float* rgb     = (const float*)d_in[0];
    const float* density = (const float*)d_in[1];
    const float* dist    = (const float*)d_in[2];
    float* out = (float*)d_out;

    const int n_rays = in_sizes[2] / N_SAMPLES;

    const int threads = 256;                       // 8 warps = 8 rays / block
    const int rays_per_block = threads / 32;
    const int blocks = (n_rays + rays_per_block - 1) / rays_per_block;

    volrend_kernel<<<blocks, threads>>>(rgb, density, dist, out, n_rays);
}